// round 8
// baseline (speedup 1.0000x reference)
#include <cuda_runtime.h>
#include <cstdint>

#define NEG (-1e30f)
#define TLAST 512
#define NQ4 8404992          /* 513*65536/4 */

// ---- shared memory layout (byte offsets) ----
#define OFF_WORK 0            /* 256 floats  : scan vector            */
#define OFF_RX   1024         /* 2*256 floats: DSMEM receive buffers  */
#define OFF_REDF 3072         /* 1024 floats : reduction values       */
#define OFF_REDI 7168         /* 1024 ints   : reduction indices      */
#define OFF_MBAR 11264        /* 2 mbarriers                          */
#define OFF_BT   11296        /* 130816 B    : viterbi backtrack      */
#define SCAN_SMEM (OFF_BT + 511 * 256)   /* 142112 */

// ---------------- device globals (no allocations allowed) ----------------
__device__ float4 g_expM4[NQ4];          // exp(logM), 134.5 MB scratch
__device__ float g_ua[514 * 256];        // normalized alpha mantissa vectors
__device__ float g_vb[514 * 256];        // normalized beta  mantissa vectors
__device__ int   g_Ea[514];              // alpha exponent offsets
__device__ int   g_Eb[514];              // beta  exponent offsets
__device__ float g_Zm;                   // Z mantissa
__device__ int   g_Ez;                   // Z exponent
__device__ __align__(16) unsigned char g_idx[511 * 256];

// ---------------- kernel 1: logM = sum_k w_k f[k] (masked) + expM ----------
__global__ void k_logM(const float4* __restrict__ f4,
                       const float* __restrict__ w,
                       float4* __restrict__ out) {
    __shared__ float sw[4];
    if (threadIdx.x < 4) sw[threadIdx.x] = w[threadIdx.x];
    __syncthreads();
    int e = blockIdx.x * blockDim.x + threadIdx.x;
    if (e >= NQ4) return;
    float4 a = f4[e];
    float4 b = f4[e + NQ4];
    float4 c = f4[e + 2 * NQ4];
    float4 d = f4[e + 3 * NQ4];
    float4 r;
    r.x = fmaf(sw[3], d.x, fmaf(sw[2], c.x, fmaf(sw[1], b.x, sw[0] * a.x)));
    r.y = fmaf(sw[3], d.y, fmaf(sw[2], c.y, fmaf(sw[1], b.y, sw[0] * a.y)));
    r.z = fmaf(sw[3], d.z, fmaf(sw[2], c.z, fmaf(sw[1], b.z, sw[0] * a.z)));
    r.w = fmaf(sw[3], d.w, fmaf(sw[2], c.w, fmaf(sw[1], b.w, sw[0] * a.w)));
    int t  = e >> 14;
    int q  = e & 16383;
    int i  = q >> 6;
    int j4 = q & 63;
    if (t == 0 && i != 0) { r.x = NEG; r.y = NEG; r.z = NEG; r.w = NEG; }
    if (t == TLAST) {
        if (j4 != 0) { r.x = NEG; r.y = NEG; r.z = NEG; r.w = NEG; }
        else         { r.y = NEG; r.z = NEG; r.w = NEG; }
    }
    float4 ex;
    ex.x = __expf(r.x); ex.y = __expf(r.y); ex.z = __expf(r.z); ex.w = __expf(r.w);
    out[e] = r;
    g_expM4[e] = ex;
}

// ---------------- PTX helpers ----------------
__device__ __forceinline__ uint32_t smem_u32(const void* p) {
    uint32_t a;
    asm("{ .reg .u64 t; cvta.to.shared.u64 t, %1; cvt.u32.u64 %0, t; }" : "=r"(a) : "l"(p));
    return a;
}
__device__ __forceinline__ uint32_t mapa_u32(uint32_t a, uint32_t rank) {
    uint32_t r;
    asm("mapa.shared::cluster.u32 %0, %1, %2;" : "=r"(r) : "r"(a), "r"(rank));
    return r;
}
__device__ __forceinline__ void st_remote_f32(uint32_t a, float v) {
    asm volatile("st.shared::cluster.f32 [%0], %1;" :: "r"(a), "f"(v) : "memory");
}
__device__ __forceinline__ void mbar_arrive_remote(uint32_t a) {
    asm volatile("mbarrier.arrive.release.cluster.shared::cluster.b64 _, [%0];"
                 :: "r"(a) : "memory");
}
__device__ __forceinline__ void mbar_init(uint32_t a, uint32_t cnt) {
    asm volatile("mbarrier.init.shared.b64 [%0], %1;" :: "r"(a), "r"(cnt) : "memory");
}
__device__ __forceinline__ void mbar_wait(uint32_t a, uint32_t parity) {
    asm volatile(
        "{\n\t.reg .pred P;\n"
        "W%=:\n\t"
        "mbarrier.try_wait.parity.acquire.cluster.shared::cta.b64 P, [%0], %1, 0x989680;\n\t"
        "@!P bra W%=;\n\t}"
        :: "r"(a), "r"(parity) : "memory");
}
__device__ __forceinline__ void cluster_sync_all() {
    asm volatile("barrier.cluster.arrive.aligned;" ::: "memory");
    asm volatile("barrier.cluster.wait.aligned;" ::: "memory");
}

// ---------------- kernel 2: the three scans --------------------------------
// grid = 24 CTAs, cluster (8,1,1): cluster 0 = alpha, 1 = beta, 2 = viterbi
__global__ void __cluster_dims__(8, 1, 1) __launch_bounds__(256, 1)
k_scan(const float* __restrict__ lM, float* __restrict__ path_out) {
    extern __shared__ unsigned char smem_raw[];
    float* s_work = reinterpret_cast<float*>(smem_raw + OFF_WORK);
    float* s_rx   = reinterpret_cast<float*>(smem_raw + OFF_RX);
    float* s_redf = reinterpret_cast<float*>(smem_raw + OFF_REDF);
    int*   s_redi = reinterpret_cast<int*>(smem_raw + OFF_REDI);
    unsigned char* s_bt = smem_raw + OFF_BT;

    const int tid   = threadIdx.x;
    const int role  = blockIdx.x >> 3;
    const int crank = blockIdx.x & 7;
    const uint32_t sbase = smem_u32(smem_raw);

    if (tid == 0) {
        mbar_init(sbase + OFF_MBAR + 0, 256);
        mbar_init(sbase + OFF_MBAR + 8, 256);
    }
    __syncthreads();
    cluster_sync_all();            // all peers' mbarriers initialized

    uint32_t pb[8];
#pragma unroll
    for (int p = 0; p < 8; ++p) pb[p] = mapa_u32(sbase, p);

    const int lane = tid & 31;
    const int wrp  = tid >> 5;

    if (role == 0) {
        // ============ forward alpha scan, linear space, 2^k renorm ============
        const int jq = tid & 7;
        const int ig = tid >> 3;
        const int jbase = crank * 32;
        s_work[tid] = (tid == 0) ? 1.f : 0.f;
        if (crank == 0) {
            g_ua[tid] = (tid == 0) ? 1.f : 0.f;
            if (tid == 0) g_Ea[0] = 0;
        }
        int Ea = 0;
        __syncthreads();

        float4 tile[8];
        {
            const float4* p = g_expM4 + (jbase >> 2) + jq;
#pragma unroll
            for (int m = 0; m < 8; ++m) tile[m] = p[(ig * 8 + m) * 64];
        }
        for (int t = 0; t <= TLAST; ++t) {
            const int buf = t & 1;
            const int ph  = (t >> 1) & 1;
            float ax = 0.f, ay = 0.f, az = 0.f, aw = 0.f;
#pragma unroll
            for (int m = 0; m < 8; ++m) {
                float a = s_work[ig * 8 + m];
                ax = fmaf(a, tile[m].x, ax);
                ay = fmaf(a, tile[m].y, ay);
                az = fmaf(a, tile[m].z, az);
                aw = fmaf(a, tile[m].w, aw);
            }
            if (t < TLAST) {   // prefetch next tile; overlaps reduce+exchange
                const float4* p = g_expM4 + (size_t)(t + 1) * 16384 + (jbase >> 2) + jq;
#pragma unroll
                for (int m = 0; m < 8; ++m) tile[m] = p[(ig * 8 + m) * 64];
            }
            // in-warp reduce over the 4 ig-groups of this warp
            ax += __shfl_xor_sync(0xffffffffu, ax, 8);
            ay += __shfl_xor_sync(0xffffffffu, ay, 8);
            az += __shfl_xor_sync(0xffffffffu, az, 8);
            aw += __shfl_xor_sync(0xffffffffu, aw, 8);
            ax += __shfl_xor_sync(0xffffffffu, ax, 16);
            ay += __shfl_xor_sync(0xffffffffu, ay, 16);
            az += __shfl_xor_sync(0xffffffffu, az, 16);
            aw += __shfl_xor_sync(0xffffffffu, aw, 16);
            if (lane < 8)
                *reinterpret_cast<float4*>(s_redf + wrp * 32 + lane * 4) =
                    make_float4(ax, ay, az, aw);
            __syncthreads();
            if (tid < 32) {
                float S = ((s_redf[tid] + s_redf[32 + tid]) + (s_redf[64 + tid] + s_redf[96 + tid]))
                        + ((s_redf[128 + tid] + s_redf[160 + tid]) + (s_redf[192 + tid] + s_redf[224 + tid]));
                uint32_t orx = OFF_RX + (uint32_t)buf * 1024 + (uint32_t)(jbase + tid) * 4;
                uint32_t omb = OFF_MBAR + (uint32_t)buf * 8;
#pragma unroll
                for (int p = 0; p < 8; ++p) st_remote_f32(pb[p] + orx, S);
#pragma unroll
                for (int p = 0; p < 8; ++p) mbar_arrive_remote(pb[p] + omb);
            }
            mbar_wait(sbase + OFF_MBAR + buf * 8, ph);
            float S0 = s_rx[buf * 256];
            float Sv = s_rx[buf * 256 + tid];
            int e0 = (__float_as_int(S0) >> 23) - 127;
            float scale = __int_as_float((127 - e0) << 23);   // exact 2^-e0
            float u = Sv * scale;
            s_work[tid] = u;
            if ((unsigned)(tid - jbase) < 32u) g_ua[(t + 1) * 256 + tid] = u;
            Ea += e0;
            if (crank == 0 && tid == 0) g_Ea[t + 1] = Ea;
            __syncthreads();
        }
        if (crank == 0 && tid == 0) {
            float Zm = 0.f;
            for (int j = 0; j < 256; ++j) Zm += s_work[j];
            g_Zm = Zm;
            g_Ez = Ea;
        }
    } else if (role == 1) {
        // ============ backward beta scan, linear space, 2^k renorm ============
        const int jq = tid & 7;
        const int iloc = tid >> 3;
        const int ibase = crank * 32;
        s_work[tid] = (tid == 0) ? 1.f : 0.f;
        if (crank == 0) {
            g_vb[513 * 256 + tid] = (tid == 0) ? 1.f : 0.f;
            if (tid == 0) g_Eb[513] = 0;
        }
        int Eb = 0;
        __syncthreads();

        float4 tile[8];
        {
            const float4* p = g_expM4 + (size_t)TLAST * 16384 + (ibase + iloc) * 64;
#pragma unroll
            for (int m = 0; m < 8; ++m) tile[m] = p[jq + m * 8];
        }
        for (int k = 0; k <= TLAST; ++k) {
            const int t = TLAST - k;
            const int buf = k & 1;
            const int ph  = (k >> 1) & 1;
            float acc = 0.f;
#pragma unroll
            for (int m = 0; m < 8; ++m) {
                const float4 b = *reinterpret_cast<const float4*>(s_work + (jq + m * 8) * 4);
                acc = fmaf(tile[m].x, b.x, acc);
                acc = fmaf(tile[m].y, b.y, acc);
                acc = fmaf(tile[m].z, b.z, acc);
                acc = fmaf(tile[m].w, b.w, acc);
            }
            if (t > 0) {
                const float4* p = g_expM4 + (size_t)(t - 1) * 16384 + (ibase + iloc) * 64;
#pragma unroll
                for (int m = 0; m < 8; ++m) tile[m] = p[jq + m * 8];
            }
            acc += __shfl_xor_sync(0xffffffffu, acc, 1);
            acc += __shfl_xor_sync(0xffffffffu, acc, 2);
            acc += __shfl_xor_sync(0xffffffffu, acc, 4);
            if (jq == 0) {
                uint32_t orx = OFF_RX + (uint32_t)buf * 1024 + (uint32_t)(ibase + iloc) * 4;
                uint32_t omb = OFF_MBAR + (uint32_t)buf * 8;
#pragma unroll
                for (int p = 0; p < 8; ++p) st_remote_f32(pb[p] + orx, acc);
#pragma unroll
                for (int p = 0; p < 8; ++p) mbar_arrive_remote(pb[p] + omb);
            }
            mbar_wait(sbase + OFF_MBAR + buf * 8, ph);
            float S0 = s_rx[buf * 256];
            float Sv = s_rx[buf * 256 + tid];
            int e0 = (__float_as_int(S0) >> 23) - 127;
            float scale = __int_as_float((127 - e0) << 23);
            float v = Sv * scale;
            s_work[tid] = v;
            if ((unsigned)(tid - ibase) < 32u) g_vb[t * 256 + tid] = v;
            Eb += e0;
            if (crank == 0 && tid == 0) g_Eb[t] = Eb;
            __syncthreads();
        }
    } else {
        // ============ viterbi (max-plus, exact log space) + backtrack ============
        const int jq = tid & 7;
        const int ig = tid >> 3;
        const int jbase = crank * 32;
        s_work[tid] = lM[tid];          // delta0 = logM[0, 0, :]
        __syncthreads();

        float4 tile[8];
        {
            const float4* p = reinterpret_cast<const float4*>(lM + 65536) + (jbase >> 2) + jq;
#pragma unroll
            for (int m = 0; m < 8; ++m) tile[m] = p[(ig * 8 + m) * 64];
        }
        for (int s = 1; s <= 511; ++s) {
            const int buf = (s - 1) & 1;
            const int ph  = ((s - 1) >> 1) & 1;
            float ninf = -__int_as_float(0x7f800000);
            float bx = ninf, by = ninf, bz = ninf, bw = ninf;
            int ixx = 0, ixy = 0, ixz = 0, ixw = 0;
#pragma unroll
            for (int m = 0; m < 8; ++m) {
                int i = ig * 8 + m;
                float d = s_work[i];
                float t0 = d + tile[m].x; if (t0 > bx) { bx = t0; ixx = i; }
                float t1 = d + tile[m].y; if (t1 > by) { by = t1; ixy = i; }
                float t2 = d + tile[m].z; if (t2 > bz) { bz = t2; ixz = i; }
                float t3 = d + tile[m].w; if (t3 > bw) { bw = t3; ixw = i; }
            }
            if (s < 511) {
                const float4* p = reinterpret_cast<const float4*>(lM + (size_t)(s + 1) * 65536)
                                  + (jbase >> 2) + jq;
#pragma unroll
                for (int m = 0; m < 8; ++m) tile[m] = p[(ig * 8 + m) * 64];
            }
            // in-warp first-max merge over ig groups (self = lower i; strict >)
            {
                float o; int oi;
                o  = __shfl_xor_sync(0xffffffffu, bx, 8);
                oi = __shfl_xor_sync(0xffffffffu, ixx, 8);
                if (o > bx) { bx = o; ixx = oi; }
                o  = __shfl_xor_sync(0xffffffffu, by, 8);
                oi = __shfl_xor_sync(0xffffffffu, ixy, 8);
                if (o > by) { by = o; ixy = oi; }
                o  = __shfl_xor_sync(0xffffffffu, bz, 8);
                oi = __shfl_xor_sync(0xffffffffu, ixz, 8);
                if (o > bz) { bz = o; ixz = oi; }
                o  = __shfl_xor_sync(0xffffffffu, bw, 8);
                oi = __shfl_xor_sync(0xffffffffu, ixw, 8);
                if (o > bw) { bw = o; ixw = oi; }
                o  = __shfl_xor_sync(0xffffffffu, bx, 16);
                oi = __shfl_xor_sync(0xffffffffu, ixx, 16);
                if (o > bx) { bx = o; ixx = oi; }
                o  = __shfl_xor_sync(0xffffffffu, by, 16);
                oi = __shfl_xor_sync(0xffffffffu, ixy, 16);
                if (o > by) { by = o; ixy = oi; }
                o  = __shfl_xor_sync(0xffffffffu, bz, 16);
                oi = __shfl_xor_sync(0xffffffffu, ixz, 16);
                if (o > bz) { bz = o; ixz = oi; }
                o  = __shfl_xor_sync(0xffffffffu, bw, 16);
                oi = __shfl_xor_sync(0xffffffffu, ixw, 16);
                if (o > bw) { bw = o; ixw = oi; }
            }
            if (lane < 8) {
                *reinterpret_cast<float4*>(s_redf + wrp * 32 + lane * 4) =
                    make_float4(bx, by, bz, bw);
                *reinterpret_cast<int4*>(s_redi + wrp * 32 + lane * 4) =
                    make_int4(ixx, ixy, ixz, ixw);
            }
            __syncthreads();
            if (tid < 32) {
                float bv = s_redf[tid];
                int bi = s_redi[tid];
#pragma unroll
                for (int g = 1; g < 8; ++g) {          // ascending warp => ascending i
                    float v = s_redf[g * 32 + tid];
                    if (v > bv) { bv = v; bi = s_redi[g * 32 + tid]; }
                }
                g_idx[(s - 1) * 256 + jbase + tid] = (unsigned char)bi;
                uint32_t orx = OFF_RX + (uint32_t)buf * 1024 + (uint32_t)(jbase + tid) * 4;
                uint32_t omb = OFF_MBAR + (uint32_t)buf * 8;
#pragma unroll
                for (int p = 0; p < 8; ++p) st_remote_f32(pb[p] + orx, bv);
#pragma unroll
                for (int p = 0; p < 8; ++p) mbar_arrive_remote(pb[p] + omb);
            }
            mbar_wait(sbase + OFF_MBAR + buf * 8, ph);
            s_work[tid] = s_rx[buf * 256 + tid];
            __syncthreads();
        }
        cluster_sync_all();     // make peers' g_idx stores visible to crank 0
        if (crank == 0) {
            const uint32_t* src = reinterpret_cast<const uint32_t*>(g_idx);
            uint32_t* dst = reinterpret_cast<uint32_t*>(s_bt);
            for (int k = tid; k < (511 * 256) / 4; k += 256) dst[k] = src[k];
            __syncthreads();
            if (tid == 0) {
                float bv = s_work[0];
                int li = 0;
                for (int j = 1; j < 256; ++j) {
                    float v = s_work[j];
                    if (v > bv) { bv = v; li = j; }
                }
                path_out[511] = (float)li;
                int y = li;
                for (int s2 = 510; s2 >= 0; --s2) {
                    y = s_bt[s2 * 256 + y];
                    path_out[s2] = (float)y;
                }
            }
        }
    }
}

// ------- kernel 3: p12 = expM * u[t][i] * v[t+1][j] * 2^E / Zm (no MUFU) ----
__global__ void k_p12(float4* __restrict__ m) {
    int e = blockIdx.x * blockDim.x + threadIdx.x;
    if (e >= NQ4) return;
    int t  = e >> 14;
    int q  = e & 16383;
    int i  = q >> 6;
    int j4 = q & 63;
    float4 v = g_expM4[e];
    float ui = g_ua[t * 256 + i];
    const float4 B = *reinterpret_cast<const float4*>(&g_vb[(t + 1) * 256 + j4 * 4]);
    int E = g_Ea[t] + g_Eb[t + 1] - g_Ez;
    float a = ui * ldexpf(__fdividef(1.0f, g_Zm), E);
    float4 r;
    r.x = v.x * a * B.x;
    r.y = v.y * a * B.y;
    r.z = v.z * a * B.z;
    r.w = v.w * a * B.w;
    m[e] = r;
}

// ---------------- launcher ----------------
extern "C" void kernel_launch(void* const* d_in, const int* in_sizes, int n_in,
                              void* d_out, int out_size) {
    const float* f = (const float*)d_in[0];
    const float* w = (const float*)d_in[1];
    float* out = (float*)d_out;

    cudaFuncSetAttribute(k_scan, cudaFuncAttributeMaxDynamicSharedMemorySize, SCAN_SMEM);

    const int nb = (NQ4 + 255) / 256;   // 32832
    k_logM<<<nb, 256>>>((const float4*)f, w, (float4*)out);
    k_scan<<<24, 256, SCAN_SMEM>>>(out, out + (out_size - 512));
    k_p12<<<nb, 256>>>((float4*)out);
}

// round 9
// speedup vs baseline: 1.7663x; 1.7663x over previous
#include <cuda_runtime.h>
#include <cstdint>

#define NEG (-1e30f)
#define TLAST 512
#define NQ4 8404992          /* 513*65536/4 */

// ---- shared memory layout (byte offsets) ----
#define OFF_RX   0            /* 2*256 floats: DSMEM exchange buffers */
#define OFF_REDF 2048         /* 1024 floats : reduction values       */
#define OFF_REDI 6144         /* 1024 ints   : reduction indices      */
#define OFF_MBAR 10240        /* 2 mbarriers (8B each)                */
#define OFF_BT   10256        /* 130816 B    : viterbi backtrack      */
#define SCAN_SMEM (OFF_BT + 511 * 256)   /* 141072 */

// ---------------- device globals (no allocations allowed) ----------------
__device__ float4 g_expM4[NQ4];          // exp(logM), 134.5 MB scratch
__device__ float g_ua[514 * 256];        // normalized alpha mantissa vectors
__device__ float g_vb[514 * 256];        // normalized beta  mantissa vectors
__device__ int   g_Ea[514];              // alpha exponent offsets
__device__ int   g_Eb[514];              // beta  exponent offsets
__device__ float g_Zm;                   // Z mantissa
__device__ int   g_Ez;                   // Z exponent
__device__ __align__(16) unsigned char g_idx[511 * 256];

// ---------------- kernel 1: logM = sum_k w_k f[k] (masked) + expM ----------
__global__ void k_logM(const float4* __restrict__ f4,
                       const float* __restrict__ w,
                       float4* __restrict__ out) {
    __shared__ float sw[4];
    if (threadIdx.x < 4) sw[threadIdx.x] = w[threadIdx.x];
    __syncthreads();
    int e = blockIdx.x * blockDim.x + threadIdx.x;
    if (e >= NQ4) return;
    float4 a = f4[e];
    float4 b = f4[e + NQ4];
    float4 c = f4[e + 2 * NQ4];
    float4 d = f4[e + 3 * NQ4];
    float4 r;
    r.x = fmaf(sw[3], d.x, fmaf(sw[2], c.x, fmaf(sw[1], b.x, sw[0] * a.x)));
    r.y = fmaf(sw[3], d.y, fmaf(sw[2], c.y, fmaf(sw[1], b.y, sw[0] * a.y)));
    r.z = fmaf(sw[3], d.z, fmaf(sw[2], c.z, fmaf(sw[1], b.z, sw[0] * a.z)));
    r.w = fmaf(sw[3], d.w, fmaf(sw[2], c.w, fmaf(sw[1], b.w, sw[0] * a.w)));
    int t  = e >> 14;
    int q  = e & 16383;
    int i  = q >> 6;
    int j4 = q & 63;
    if (t == 0 && i != 0) { r.x = NEG; r.y = NEG; r.z = NEG; r.w = NEG; }
    if (t == TLAST) {
        if (j4 != 0) { r.x = NEG; r.y = NEG; r.z = NEG; r.w = NEG; }
        else         { r.y = NEG; r.z = NEG; r.w = NEG; }
    }
    float4 ex;
    ex.x = __expf(r.x); ex.y = __expf(r.y); ex.z = __expf(r.z); ex.w = __expf(r.w);
    out[e] = r;
    g_expM4[e] = ex;
}

// ---------------- PTX helpers ----------------
__device__ __forceinline__ uint32_t smem_u32(const void* p) {
    uint32_t a;
    asm("{ .reg .u64 t; cvta.to.shared.u64 t, %1; cvt.u32.u64 %0, t; }" : "=r"(a) : "l"(p));
    return a;
}
__device__ __forceinline__ uint32_t mapa_u32(uint32_t a, uint32_t rank) {
    uint32_t r;
    asm("mapa.shared::cluster.u32 %0, %1, %2;" : "=r"(r) : "r"(a), "r"(rank));
    return r;
}
__device__ __forceinline__ void st_remote_f32(uint32_t a, float v) {
    asm volatile("st.shared::cluster.f32 [%0], %1;" :: "r"(a), "f"(v) : "memory");
}
__device__ __forceinline__ void mbar_arrive_remote(uint32_t a) {
    asm volatile("mbarrier.arrive.release.cluster.shared::cluster.b64 _, [%0];"
                 :: "r"(a) : "memory");
}
__device__ __forceinline__ void mbar_init(uint32_t a, uint32_t cnt) {
    asm volatile("mbarrier.init.shared.b64 [%0], %1;" :: "r"(a), "r"(cnt) : "memory");
}
__device__ __forceinline__ void mbar_wait(uint32_t a, uint32_t parity) {
    asm volatile(
        "{\n\t.reg .pred P;\n"
        "W%=:\n\t"
        "mbarrier.try_wait.parity.acquire.cluster.shared::cta.b64 P, [%0], %1, 0x989680;\n\t"
        "@!P bra W%=;\n\t}"
        :: "r"(a), "r"(parity) : "memory");
}
__device__ __forceinline__ void cluster_sync_all() {
    asm volatile("barrier.cluster.arrive.aligned;" ::: "memory");
    asm volatile("barrier.cluster.wait.aligned;" ::: "memory");
}

// ============================================================================
// per-step bodies (forceinlined; two tile buffers give depth-2 prefetch)
// ============================================================================

__device__ __forceinline__ void alpha_step(
    int t, float4 (&tile)[8], float* s_rx, float* s_redf,
    uint32_t sbase, const uint32_t (&pb)[8],
    int tid, int lane, int wrp, int jq, int ig, int jbase, int crank, int& Ea)
{
    const int wbuf = t & 1;
    const int rb   = ((t + 1) & 1) * 256;
    const int ph   = (t >> 1) & 1;
    // normalization from S0 of the incoming vector (exact power of 2)
    float S0 = s_rx[rb];
    int e0 = (__float_as_int(S0) >> 23) - 127;
    float scale = __int_as_float((127 - e0) << 23);
    Ea += e0;
    if (wrp == crank)
        g_ua[t * 256 + jbase + lane] = s_rx[rb + jbase + lane] * scale;
    if (crank == 0 && tid == 0) g_Ea[t] = Ea;
    // GEMV partial: columns j = jbase + jq*4 .. +3, rows ig*8..ig*8+7
    float ax = 0.f, ay = 0.f, az = 0.f, aw = 0.f;
#pragma unroll
    for (int m = 0; m < 8; ++m) {
        float a = s_rx[rb + ig * 8 + m];
        ax = fmaf(a, tile[m].x, ax);
        ay = fmaf(a, tile[m].y, ay);
        az = fmaf(a, tile[m].z, az);
        aw = fmaf(a, tile[m].w, aw);
    }
    if (t + 2 <= TLAST) {   // depth-2 prefetch into this buffer
        const float4* p = g_expM4 + (size_t)(t + 2) * 16384 + (jbase >> 2) + jq;
#pragma unroll
        for (int m = 0; m < 8; ++m) tile[m] = p[(ig * 8 + m) * 64];
    }
    ax *= scale; ay *= scale; az *= scale; aw *= scale;
    ax += __shfl_xor_sync(0xffffffffu, ax, 8);
    ay += __shfl_xor_sync(0xffffffffu, ay, 8);
    az += __shfl_xor_sync(0xffffffffu, az, 8);
    aw += __shfl_xor_sync(0xffffffffu, aw, 8);
    ax += __shfl_xor_sync(0xffffffffu, ax, 16);
    ay += __shfl_xor_sync(0xffffffffu, ay, 16);
    az += __shfl_xor_sync(0xffffffffu, az, 16);
    aw += __shfl_xor_sync(0xffffffffu, aw, 16);
    if (lane < 8)
        *reinterpret_cast<float4*>(s_redf + wrp * 32 + lane * 4) =
            make_float4(ax, ay, az, aw);
    __syncthreads();
    if (wrp == 0) {
        float S = ((s_redf[tid] + s_redf[32 + tid]) + (s_redf[64 + tid] + s_redf[96 + tid]))
                + ((s_redf[128 + tid] + s_redf[160 + tid]) + (s_redf[192 + tid] + s_redf[224 + tid]));
        uint32_t orx = OFF_RX + (uint32_t)wbuf * 1024 + (uint32_t)(jbase + tid) * 4;
#pragma unroll
        for (int p = 0; p < 8; ++p) st_remote_f32(pb[p] + orx, S);
        __syncwarp();
        if (lane < 8) mbar_arrive_remote(pb[lane] + OFF_MBAR + wbuf * 8);
    }
    mbar_wait(sbase + OFF_MBAR + wbuf * 8, ph);
}

__device__ __forceinline__ void beta_step(
    int k, float4 (&tile)[8], float* s_rx,
    uint32_t sbase, const uint32_t (&pb)[8],
    int tid, int lane, int jq, int iloc, int ibase, int crank, int& Eb)
{
    const int t    = TLAST - k;      // matrix index this step
    const int wbuf = k & 1;
    const int rb   = ((k + 1) & 1) * 256;
    const int ph   = (k >> 1) & 1;
    float S0 = s_rx[rb];
    int e0 = (__float_as_int(S0) >> 23) - 127;
    float scale = __int_as_float((127 - e0) << 23);
    Eb += e0;
    if ((tid >> 5) == crank)
        g_vb[(t + 1) * 256 + ibase + lane] = s_rx[rb + ibase + lane] * scale;
    if (crank == 0 && tid == 0) g_Eb[t + 1] = Eb;
    float acc = 0.f;
#pragma unroll
    for (int m = 0; m < 8; ++m) {
        const float4 b = *reinterpret_cast<const float4*>(s_rx + rb + (jq + m * 8) * 4);
        acc = fmaf(tile[m].x, b.x, acc);
        acc = fmaf(tile[m].y, b.y, acc);
        acc = fmaf(tile[m].z, b.z, acc);
        acc = fmaf(tile[m].w, b.w, acc);
    }
    if (t >= 2) {
        const float4* p = g_expM4 + (size_t)(t - 2) * 16384 + (ibase + iloc) * 64;
#pragma unroll
        for (int m = 0; m < 8; ++m) tile[m] = p[jq + m * 8];
    }
    acc *= scale;
    acc += __shfl_xor_sync(0xffffffffu, acc, 1);
    acc += __shfl_xor_sync(0xffffffffu, acc, 2);
    acc += __shfl_xor_sync(0xffffffffu, acc, 4);
    if (jq == 0) {
        uint32_t orx = OFF_RX + (uint32_t)wbuf * 1024 + (uint32_t)(ibase + iloc) * 4;
#pragma unroll
        for (int p = 0; p < 8; ++p) st_remote_f32(pb[p] + orx, acc);
    }
    __syncthreads();
    if (tid < 8) mbar_arrive_remote(pb[tid] + OFF_MBAR + wbuf * 8);
    mbar_wait(sbase + OFF_MBAR + wbuf * 8, ph);
}

__device__ __forceinline__ void vit_step(
    int s, float4 (&tile)[8], const float* lM, float* s_rx, float* s_redf, int* s_redi,
    uint32_t sbase, const uint32_t (&pb)[8],
    int tid, int lane, int wrp, int jq, int ig, int jbase)
{
    const int k    = s - 1;
    const int wbuf = k & 1;
    const int rb   = ((k + 1) & 1) * 256;
    const int ph   = (k >> 1) & 1;
    float ninf = -__int_as_float(0x7f800000);
    float bx = ninf, by = ninf, bz = ninf, bw = ninf;
    int ixx = 0, ixy = 0, ixz = 0, ixw = 0;
#pragma unroll
    for (int m = 0; m < 8; ++m) {
        int i = ig * 8 + m;
        float d = s_rx[rb + i];
        float t0 = d + tile[m].x; if (t0 > bx) { bx = t0; ixx = i; }
        float t1 = d + tile[m].y; if (t1 > by) { by = t1; ixy = i; }
        float t2 = d + tile[m].z; if (t2 > bz) { bz = t2; ixz = i; }
        float t3 = d + tile[m].w; if (t3 > bw) { bw = t3; ixw = i; }
    }
    if (s + 2 <= 511) {
        const float4* p = reinterpret_cast<const float4*>(lM + (size_t)(s + 2) * 65536)
                          + (jbase >> 2) + jq;
#pragma unroll
        for (int m = 0; m < 8; ++m) tile[m] = p[(ig * 8 + m) * 64];
    }
    // in-warp first-max merge (self = lower i; strict >; only lanes<8 results used)
    {
        float o; int oi;
        o = __shfl_xor_sync(0xffffffffu, bx, 8);  oi = __shfl_xor_sync(0xffffffffu, ixx, 8);
        if (o > bx) { bx = o; ixx = oi; }
        o = __shfl_xor_sync(0xffffffffu, by, 8);  oi = __shfl_xor_sync(0xffffffffu, ixy, 8);
        if (o > by) { by = o; ixy = oi; }
        o = __shfl_xor_sync(0xffffffffu, bz, 8);  oi = __shfl_xor_sync(0xffffffffu, ixz, 8);
        if (o > bz) { bz = o; ixz = oi; }
        o = __shfl_xor_sync(0xffffffffu, bw, 8);  oi = __shfl_xor_sync(0xffffffffu, ixw, 8);
        if (o > bw) { bw = o; ixw = oi; }
        o = __shfl_xor_sync(0xffffffffu, bx, 16); oi = __shfl_xor_sync(0xffffffffu, ixx, 16);
        if (o > bx) { bx = o; ixx = oi; }
        o = __shfl_xor_sync(0xffffffffu, by, 16); oi = __shfl_xor_sync(0xffffffffu, ixy, 16);
        if (o > by) { by = o; ixy = oi; }
        o = __shfl_xor_sync(0xffffffffu, bz, 16); oi = __shfl_xor_sync(0xffffffffu, ixz, 16);
        if (o > bz) { bz = o; ixz = oi; }
        o = __shfl_xor_sync(0xffffffffu, bw, 16); oi = __shfl_xor_sync(0xffffffffu, ixw, 16);
        if (o > bw) { bw = o; ixw = oi; }
    }
    if (lane < 8) {
        *reinterpret_cast<float4*>(s_redf + wrp * 32 + lane * 4) = make_float4(bx, by, bz, bw);
        *reinterpret_cast<int4*>(s_redi + wrp * 32 + lane * 4) = make_int4(ixx, ixy, ixz, ixw);
    }
    __syncthreads();
    if (wrp == 0) {
        float bv = s_redf[tid];
        int bi = s_redi[tid];
#pragma unroll
        for (int g = 1; g < 8; ++g) {          // ascending warp => ascending i
            float v = s_redf[g * 32 + tid];
            if (v > bv) { bv = v; bi = s_redi[g * 32 + tid]; }
        }
        g_idx[(size_t)k * 256 + jbase + tid] = (unsigned char)bi;
        uint32_t orx = OFF_RX + (uint32_t)wbuf * 1024 + (uint32_t)(jbase + tid) * 4;
#pragma unroll
        for (int p = 0; p < 8; ++p) st_remote_f32(pb[p] + orx, bv);
        __syncwarp();
        if (lane < 8) mbar_arrive_remote(pb[lane] + OFF_MBAR + wbuf * 8);
    }
    mbar_wait(sbase + OFF_MBAR + wbuf * 8, ph);
}

// ---------------- kernel 2: the three scans --------------------------------
// grid = 24 CTAs, cluster (8,1,1): cluster 0 = alpha, 1 = beta, 2 = viterbi
__global__ void __cluster_dims__(8, 1, 1) __launch_bounds__(256, 1)
k_scan(const float* __restrict__ lM, float* __restrict__ path_out) {
    extern __shared__ unsigned char smem_raw[];
    float* s_rx   = reinterpret_cast<float*>(smem_raw + OFF_RX);
    float* s_redf = reinterpret_cast<float*>(smem_raw + OFF_REDF);
    int*   s_redi = reinterpret_cast<int*>(smem_raw + OFF_REDI);
    unsigned char* s_bt = smem_raw + OFF_BT;

    const int tid   = threadIdx.x;
    const int role  = blockIdx.x >> 3;
    const int crank = blockIdx.x & 7;
    const uint32_t sbase = smem_u32(smem_raw);

    if (tid == 0) {
        mbar_init(sbase + OFF_MBAR + 0, 8);   // one arrive per CTA
        mbar_init(sbase + OFF_MBAR + 8, 8);
    }
    __syncthreads();
    cluster_sync_all();            // all peers' mbarriers initialized

    uint32_t pb[8];
#pragma unroll
    for (int p = 0; p < 8; ++p) pb[p] = mapa_u32(sbase, p);

    const int lane = tid & 31;
    const int wrp  = tid >> 5;

    if (role == 0) {
        // ============ forward alpha scan ============
        const int jq = tid & 7;
        const int ig = tid >> 3;
        const int jbase = crank * 32;
        s_rx[256 + tid] = (tid == 0) ? 1.f : 0.f;   // v0 in buffer 1
        int Ea = 0;
        __syncthreads();

        float4 tA[8], tB[8];
        {
            const float4* p0 = g_expM4 + (jbase >> 2) + jq;
            const float4* p1 = g_expM4 + 16384 + (jbase >> 2) + jq;
#pragma unroll
            for (int m = 0; m < 8; ++m) { tA[m] = p0[(ig * 8 + m) * 64]; tB[m] = p1[(ig * 8 + m) * 64]; }
        }
        for (int t = 0; t < TLAST; t += 2) {
            alpha_step(t,     tA, s_rx, s_redf, sbase, pb, tid, lane, wrp, jq, ig, jbase, crank, Ea);
            alpha_step(t + 1, tB, s_rx, s_redf, sbase, pb, tid, lane, wrp, jq, ig, jbase, crank, Ea);
        }
        alpha_step(TLAST, tA, s_rx, s_redf, sbase, pb, tid, lane, wrp, jq, ig, jbase, crank, Ea);
        // tail: t = 513 vector sits in buffer (512&1)=0
        {
            float S0 = s_rx[0];
            int e0 = (__float_as_int(S0) >> 23) - 127;
            float scale = __int_as_float((127 - e0) << 23);
            Ea += e0;
            if (wrp == crank)
                g_ua[513 * 256 + jbase + lane] = s_rx[jbase + lane] * scale;
            if (crank == 0 && tid == 0) {
                g_Ea[513] = Ea;
                float Zm = 0.f;
                for (int j = 0; j < 256; ++j) Zm += s_rx[j] * scale;
                g_Zm = Zm;
                g_Ez = Ea;
            }
        }
    } else if (role == 1) {
        // ============ backward beta scan ============
        const int jq = tid & 7;
        const int iloc = tid >> 3;
        const int ibase = crank * 32;
        s_rx[256 + tid] = (tid == 0) ? 1.f : 0.f;   // beta_{513} in buffer 1
        int Eb = 0;
        __syncthreads();

        float4 tA[8], tB[8];
        {
            const float4* p0 = g_expM4 + (size_t)TLAST * 16384 + (ibase + iloc) * 64;
            const float4* p1 = g_expM4 + (size_t)(TLAST - 1) * 16384 + (ibase + iloc) * 64;
#pragma unroll
            for (int m = 0; m < 8; ++m) { tA[m] = p0[jq + m * 8]; tB[m] = p1[jq + m * 8]; }
        }
        for (int k = 0; k < TLAST; k += 2) {
            beta_step(k,     tA, s_rx, sbase, pb, tid, lane, jq, iloc, ibase, crank, Eb);
            beta_step(k + 1, tB, s_rx, sbase, pb, tid, lane, jq, iloc, ibase, crank, Eb);
        }
        beta_step(TLAST, tA, s_rx, sbase, pb, tid, lane, jq, iloc, ibase, crank, Eb);
        // tail: beta_0 vector sits in buffer 0
        {
            float S0 = s_rx[0];
            int e0 = (__float_as_int(S0) >> 23) - 127;
            float scale = __int_as_float((127 - e0) << 23);
            Eb += e0;
            if ((tid >> 5) == crank)
                g_vb[ibase + lane] = s_rx[ibase + lane] * scale;
            if (crank == 0 && tid == 0) g_Eb[0] = Eb;
        }
    } else {
        // ============ viterbi (max-plus, exact log space) + backtrack ============
        const int jq = tid & 7;
        const int ig = tid >> 3;
        const int jbase = crank * 32;
        s_rx[256 + tid] = lM[tid];     // delta_0 = logM[0, 0, :] in buffer 1
        __syncthreads();

        float4 tA[8], tB[8];
        {
            const float4* p0 = reinterpret_cast<const float4*>(lM + 65536) + (jbase >> 2) + jq;
            const float4* p1 = reinterpret_cast<const float4*>(lM + 2 * 65536) + (jbase >> 2) + jq;
#pragma unroll
            for (int m = 0; m < 8; ++m) { tA[m] = p0[(ig * 8 + m) * 64]; tB[m] = p1[(ig * 8 + m) * 64]; }
        }
        for (int s = 1; s < 511; s += 2) {
            vit_step(s,     tA, lM, s_rx, s_redf, s_redi, sbase, pb, tid, lane, wrp, jq, ig, jbase);
            vit_step(s + 1, tB, lM, s_rx, s_redf, s_redi, sbase, pb, tid, lane, wrp, jq, ig, jbase);
        }
        vit_step(511, tA, lM, s_rx, s_redf, s_redi, sbase, pb, tid, lane, wrp, jq, ig, jbase);

        cluster_sync_all();     // make peers' g_idx stores visible to crank 0
        if (crank == 0) {
            const uint32_t* src = reinterpret_cast<const uint32_t*>(g_idx);
            uint32_t* dst = reinterpret_cast<uint32_t*>(s_bt);
            for (int k = tid; k < (511 * 256) / 4; k += 256) dst[k] = src[k];
            __syncthreads();
            if (tid == 0) {
                // final delta in buffer (510&1)=0
                float bv = s_rx[0];
                int li = 0;
                for (int j = 1; j < 256; ++j) {
                    float v = s_rx[j];
                    if (v > bv) { bv = v; li = j; }
                }
                path_out[511] = (float)li;
                int y = li;
                for (int s2 = 510; s2 >= 0; --s2) {
                    y = s_bt[s2 * 256 + y];
                    path_out[s2] = (float)y;
                }
            }
        }
    }
}

// ------- kernel 3: p12 = expM * u[t][i] * v[t+1][j] * 2^E / Zm (no MUFU) ----
__global__ void k_p12(float4* __restrict__ m) {
    int e = blockIdx.x * blockDim.x + threadIdx.x;
    if (e >= NQ4) return;
    int t  = e >> 14;
    int q  = e & 16383;
    int i  = q >> 6;
    int j4 = q & 63;
    float4 v = g_expM4[e];
    float ui = g_ua[t * 256 + i];
    const float4 B = *reinterpret_cast<const float4*>(&g_vb[(t + 1) * 256 + j4 * 4]);
    int E = g_Ea[t] + g_Eb[t + 1] - g_Ez;
    float a = ui * ldexpf(__fdividef(1.0f, g_Zm), E);
    float4 r;
    r.x = v.x * a * B.x;
    r.y = v.y * a * B.y;
    r.z = v.z * a * B.z;
    r.w = v.w * a * B.w;
    m[e] = r;
}

// ---------------- launcher ----------------
extern "C" void kernel_launch(void* const* d_in, const int* in_sizes, int n_in,
                              void* d_out, int out_size) {
    const float* f = (const float*)d_in[0];
    const float* w = (const float*)d_in[1];
    float* out = (float*)d_out;

    cudaFuncSetAttribute(k_scan, cudaFuncAttributeMaxDynamicSharedMemorySize, SCAN_SMEM);

    const int nb = (NQ4 + 255) / 256;   // 32832
    k_logM<<<nb, 256>>>((const float4*)f, w, (float4*)out);
    k_scan<<<24, 256, SCAN_SMEM>>>(out, out + (out_size - 512));
    k_p12<<<nb, 256>>>((float4*)out);
}